// round 12
// baseline (speedup 1.0000x reference)
#include <cuda_runtime.h>
#include <cuda.h>
#include <cuda_bf16.h>
#include <cstdint>
#include <math.h>

#define SQ   2048   // sequence
#define DM   2048   // model dim
#define HI   16     // index heads
#define DI   128    // index head dim
#define NH   16     // attn heads
#define HD   128    // attn head dim
#define TOPKK 256
#define NEGV -1e30f

// ---------------- scratch (static device allocations) ----------------
__device__ float g_qi[SQ * DM];     // x @ wq_idx  (then hadamard per 128)
__device__ float g_ki[SQ * DI];     // x @ wk_idx  (then hadamard)
__device__ float g_iw[SQ * HI];     // x @ w_iw
__device__ float g_q [SQ * DM];     // x @ wq
__device__ float g_k [SQ * HD];     // x @ wk
__device__ float g_v [SQ * HD];     // x @ wv
__device__ float g_I [SQ * SQ];     // indexing logits (lower triangle valid)
__device__ int   g_idx[SQ * TOPKK];
__device__ int   g_nv [SQ];
__device__ float g_o [SQ * DM];     // attention output (pre-wo)

// ======================= mma.sync helpers ====================================
__device__ __forceinline__ uint32_t s2u(const void* p) {
    uint32_t a;
    asm("{ .reg .u64 t; cvta.to.shared.u64 t, %1; cvt.u32.u64 %0, t; }"
        : "=r"(a) : "l"(p));
    return a;
}

__device__ __forceinline__ void ldm_x4(uint32_t* r, uint32_t addr) {
    asm volatile("ldmatrix.sync.aligned.m8n8.x4.shared.b16 {%0,%1,%2,%3}, [%4];"
                 : "=r"(r[0]), "=r"(r[1]), "=r"(r[2]), "=r"(r[3]) : "r"(addr));
}
__device__ __forceinline__ void ldm_x2t(uint32_t* r, uint32_t addr) {
    asm volatile("ldmatrix.sync.aligned.m8n8.x2.trans.shared.b16 {%0,%1}, [%2];"
                 : "=r"(r[0]), "=r"(r[1]) : "r"(addr));
}
__device__ __forceinline__ void mma16816(float* c, const uint32_t* a, const uint32_t* b) {
    asm volatile(
        "mma.sync.aligned.m16n8k16.row.col.f32.bf16.bf16.f32 "
        "{%0,%1,%2,%3}, {%4,%5,%6,%7}, {%8,%9}, {%0,%1,%2,%3};"
        : "+f"(c[0]), "+f"(c[1]), "+f"(c[2]), "+f"(c[3])
        : "r"(a[0]), "r"(a[1]), "r"(a[2]), "r"(a[3]), "r"(b[0]), "r"(b[1]));
}

// split two fp32 into packed bf16x2 (hi) and residual bf16x2 (lo)
__device__ __forceinline__ void split2(float a, float b, uint32_t& hi, uint32_t& lo) {
    __nv_bfloat16 ah = __float2bfloat16(a), bh = __float2bfloat16(b);
    __nv_bfloat16 al = __float2bfloat16(a - __bfloat162float(ah));
    __nv_bfloat16 bl = __float2bfloat16(b - __bfloat162float(bh));
    hi = ((uint32_t)__bfloat16_as_ushort(bh) << 16) | (uint32_t)__bfloat16_as_ushort(ah);
    lo = ((uint32_t)__bfloat16_as_ushort(bl) << 16) | (uint32_t)__bfloat16_as_ushort(al);
}

// ---------------- split-bf16 HMMA GEMM: C[M,N] = A[M,K] @ B[K,N] -------------
// 128x128 CTA tile, 8 warps (2x4), warp tile 64x32, BK=32, mma.m16n8k16.
// 3-product split (hi*hi + hi*lo + lo*hi): error ~2^-18. Attention path only.
// Next chunk's global loads are register-staged before the mma section so the
// LDG latency overlaps tensor work (same math order — bit-identical results).
__global__ void __launch_bounds__(256) gemm_mma(
        const float* __restrict__ A, const float* __restrict__ B,
        float* __restrict__ C, int M, int N, int K) {
    __shared__ __nv_bfloat16 Ahi[128][40], Alo[128][40];     // 80B stride
    __shared__ __nv_bfloat16 Bhi[32][128], Blo[32][128];     // XOR-swizzled rows
    int tid = threadIdx.x, lane = tid & 31, wid = tid >> 5;
    int wm = wid >> 2, wn = wid & 3;
    int m0 = blockIdx.y * 128, n0 = blockIdx.x * 128;

    float acc[4][4][4] = {};

    uint32_t bhi_base = s2u(&Bhi[0][0]);
    uint32_t blo_base = s2u(&Blo[0][0]);

    // per-thread gather coordinates (compile-time per rep)
    int a_row = tid >> 3, a_c4 = (tid & 7) * 4;          // + rep*32 rows
    int b_row = tid >> 5, b_n4 = (tid & 31) * 4;         // + rep*8 rows

    float4 fa[4], fb[4];
    // prologue: load chunk 0
    #pragma unroll
    for (int rep = 0; rep < 4; rep++) {
        fa[rep] = *(const float4*)(A + (size_t)(m0 + a_row + rep * 32) * K + a_c4);
        fb[rep] = *(const float4*)(B + (size_t)(b_row + rep * 8) * N + n0 + b_n4);
    }

    for (int k0 = 0; k0 < K; k0 += 32) {
        // commit staged regs to smem
        #pragma unroll
        for (int rep = 0; rep < 4; rep++) {
            int row = a_row + rep * 32;
            uint32_t h0, l0, h1, l1;
            split2(fa[rep].x, fa[rep].y, h0, l0);
            split2(fa[rep].z, fa[rep].w, h1, l1);
            *(uint2*)&Ahi[row][a_c4] = make_uint2(h0, h1);
            *(uint2*)&Alo[row][a_c4] = make_uint2(l0, l1);
        }
        #pragma unroll
        for (int rep = 0; rep < 4; rep++) {
            int row = b_row + rep * 8;
            uint32_t h0, l0, h1, l1;
            split2(fb[rep].x, fb[rep].y, h0, l0);
            split2(fb[rep].z, fb[rep].w, h1, l1);
            uint32_t off = (uint32_t)(row * 256) + (((uint32_t)(b_n4 * 2)) ^ (((uint32_t)(row & 7)) << 4));
            *(uint2*)((char*)Bhi + off) = make_uint2(h0, h1);
            *(uint2*)((char*)Blo + off) = make_uint2(l0, l1);
        }
        __syncthreads();

        // prefetch next chunk into registers (latency hidden by mma below)
        if (k0 + 32 < K) {
            #pragma unroll
            for (int rep = 0; rep < 4; rep++) {
                fa[rep] = *(const float4*)(A + (size_t)(m0 + a_row + rep * 32) * K + k0 + 32 + a_c4);
                fb[rep] = *(const float4*)(B + (size_t)(k0 + 32 + b_row + rep * 8) * N + n0 + b_n4);
            }
        }

        #pragma unroll
        for (int ks = 0; ks < 2; ks++) {
            int kc = ks * 16;
            uint32_t ah[4][4], al[4][4], bh[4][2], bl[4][2];
            int r = lane & 7, mt = lane >> 3;
            int arow = (mt & 1) * 8 + r;
            int acol = kc + (mt >> 1) * 8;
            #pragma unroll
            for (int mi = 0; mi < 4; mi++) {
                int row = wm * 64 + mi * 16 + arow;
                ldm_x4(ah[mi], s2u(&Ahi[row][acol]));
                ldm_x4(al[mi], s2u(&Alo[row][acol]));
            }
            int krow = kc + (lane & 15);
            uint32_t ksw = ((uint32_t)(krow & 7)) << 4;
            #pragma unroll
            for (int ni = 0; ni < 4; ni++) {
                int nb = wn * 32 + ni * 8;
                uint32_t boff = (uint32_t)(krow * 256) + (((uint32_t)(nb * 2)) ^ ksw);
                ldm_x2t(bh[ni], bhi_base + boff);
                ldm_x2t(bl[ni], blo_base + boff);
            }
            #pragma unroll
            for (int mi = 0; mi < 4; mi++)
                #pragma unroll
                for (int ni = 0; ni < 4; ni++) {
                    mma16816(acc[mi][ni], ah[mi], bh[ni]);
                    mma16816(acc[mi][ni], ah[mi], bl[ni]);
                    mma16816(acc[mi][ni], al[mi], bh[ni]);
                }
        }
        __syncthreads();
    }

    // ---- epilogue ----
    int g = lane >> 2, tig = lane & 3;
    #pragma unroll
    for (int mi = 0; mi < 4; mi++) {
        int row = m0 + wm * 64 + mi * 16 + g;
        #pragma unroll
        for (int ni = 0; ni < 4; ni++) {
            int col = n0 + wn * 32 + ni * 8 + tig * 2;
            *(float2*)(C + (size_t)row * N + col) =
                make_float2(acc[mi][ni][0], acc[mi][ni][1]);
            *(float2*)(C + (size_t)(row + 8) * N + col) =
                make_float2(acc[mi][ni][2], acc[mi][ni][3]);
        }
    }
}

// ---------------- fused small-N GEMMs: ki / iw / k / v in ONE launch ---------
__global__ void sgemm64_multi(const float* __restrict__ A,
                              const float* __restrict__ Bki,
                              const float* __restrict__ Biw,
                              const float* __restrict__ Bk,
                              const float* __restrict__ Bv,
                              int M, int K) {
    __shared__ float As[16][64];   // [k][m]
    __shared__ float Bs[16][64];   // [k][n]
    int tid = threadIdx.x;
    int tx = tid & 15, ty = tid >> 4;
    int m0 = blockIdx.y * 64;

    const float* B; float* C; int n0; int N;
    switch (blockIdx.x) {
        case 0: B = Bki; C = g_ki; n0 = 0;  N = DI; break;
        case 1: B = Bki; C = g_ki; n0 = 64; N = DI; break;
        case 2: B = Biw; C = g_iw; n0 = 0;  N = HI; break;
        case 3: B = Bk;  C = g_k;  n0 = 0;  N = HD; break;
        case 4: B = Bk;  C = g_k;  n0 = 64; N = HD; break;
        case 5: B = Bv;  C = g_v;  n0 = 0;  N = HD; break;
        default: B = Bv; C = g_v;  n0 = 64; N = HD; break;
    }

    int a_r = tid >> 2;          // 0..63
    int a_c = (tid & 3) * 4;     // 0..12
    int b_r = tid >> 4;          // 0..15
    int b_c = (tid & 15) * 4;    // 0..60

    float acc[4][4] = {};
    float cmp[4][4] = {};

    for (int k0 = 0; k0 < K; k0 += 16) {
        float4 av = *(const float4*)(A + (size_t)(m0 + a_r) * K + k0 + a_c);
        As[a_c + 0][a_r] = av.x; As[a_c + 1][a_r] = av.y;
        As[a_c + 2][a_r] = av.z; As[a_c + 3][a_r] = av.w;
        const float* bg = B + (size_t)(k0 + b_r) * N + n0 + b_c;
        float4 bv;
        if (n0 + b_c + 3 < N) {
            bv = *(const float4*)bg;
        } else {
            bv.x = (n0 + b_c + 0 < N) ? bg[0] : 0.f;
            bv.y = (n0 + b_c + 1 < N) ? bg[1] : 0.f;
            bv.z = (n0 + b_c + 2 < N) ? bg[2] : 0.f;
            bv.w = (n0 + b_c + 3 < N) ? bg[3] : 0.f;
        }
        *(float4*)&Bs[b_r][b_c] = bv;
        __syncthreads();

        float part[4][4] = {};
        #pragma unroll
        for (int k = 0; k < 16; k++) {
            float4 a4 = *(const float4*)&As[k][ty * 4];
            float4 b4 = *(const float4*)&Bs[k][tx * 4];
            float ar[4] = {a4.x, a4.y, a4.z, a4.w};
            float br[4] = {b4.x, b4.y, b4.z, b4.w};
            #pragma unroll
            for (int i = 0; i < 4; i++)
                #pragma unroll
                for (int j = 0; j < 4; j++)
                    part[i][j] = fmaf(ar[i], br[j], part[i][j]);
        }
        #pragma unroll
        for (int i = 0; i < 4; i++)
            #pragma unroll
            for (int j = 0; j < 4; j++) {
                float y = part[i][j] - cmp[i][j];
                float t = acc[i][j] + y;
                cmp[i][j] = (t - acc[i][j]) - y;
                acc[i][j] = t;
            }
        __syncthreads();
    }
    #pragma unroll
    for (int i = 0; i < 4; i++) {
        int r = m0 + ty * 4 + i;
        #pragma unroll
        for (int j = 0; j < 4; j++) {
            int c = n0 + tx * 4 + j;
            if (c < N) C[(size_t)r * N + c] = acc[i][j];
        }
    }
}

// ---------------- big SGEMM with per-16-k-tile Kahan (index path: qi) --------
__global__ void __launch_bounds__(256) sgemm128k(
        const float* __restrict__ A, const float* __restrict__ B,
        float* __restrict__ C, int M, int N, int K) {
    __shared__ float As[2][16][132];  // 528B row stride (16B-aligned)
    __shared__ float Bs[2][16][128];
    int tid = threadIdx.x;
    int tx = tid & 15, ty = tid >> 4;
    int m0 = blockIdx.y * 128, n0 = blockIdx.x * 128;

    int ar = tid >> 1, ac = (tid & 1) * 8;   // A: 128 rows x 16 cols (2 float4)
    int br = tid >> 4, bc = (tid & 15) * 8;  // B: 16 rows x 128 cols (2 float4)

    const float* Ap = A + (size_t)(m0 + ar) * K + ac;
    const float* Bp = B + (size_t)br * N + n0 + bc;

    float acc[8][8] = {};
    float cmp[8][8] = {};

    { // tile 0
        float4 a0 = *(const float4*)Ap;
        float4 a1 = *(const float4*)(Ap + 4);
        As[0][ac + 0][ar] = a0.x; As[0][ac + 1][ar] = a0.y;
        As[0][ac + 2][ar] = a0.z; As[0][ac + 3][ar] = a0.w;
        As[0][ac + 4][ar] = a1.x; As[0][ac + 5][ar] = a1.y;
        As[0][ac + 6][ar] = a1.z; As[0][ac + 7][ar] = a1.w;
        *(float4*)&Bs[0][br][bc]     = *(const float4*)Bp;
        *(float4*)&Bs[0][br][bc + 4] = *(const float4*)(Bp + 4);
    }
    __syncthreads();

    int buf = 0;
    for (int k0 = 16; k0 <= K; k0 += 16) {
        float4 a0, a1, b0, b1;
        if (k0 < K) {
            a0 = *(const float4*)(Ap + k0);
            a1 = *(const float4*)(Ap + k0 + 4);
            b0 = *(const float4*)(Bp + (size_t)k0 * N);
            b1 = *(const float4*)(Bp + (size_t)k0 * N + 4);
        }
        float part[8][8] = {};
        #pragma unroll
        for (int k = 0; k < 16; k++) {
            float af[8], bf[8];
            *(float4*)&af[0] = *(const float4*)&As[buf][k][ty * 4];
            *(float4*)&af[4] = *(const float4*)&As[buf][k][64 + ty * 4];
            *(float4*)&bf[0] = *(const float4*)&Bs[buf][k][tx * 4];
            *(float4*)&bf[4] = *(const float4*)&Bs[buf][k][64 + tx * 4];
            #pragma unroll
            for (int i = 0; i < 8; i++)
                #pragma unroll
                for (int j = 0; j < 8; j++)
                    part[i][j] = fmaf(af[i], bf[j], part[i][j]);
        }
        #pragma unroll
        for (int i = 0; i < 8; i++)
            #pragma unroll
            for (int j = 0; j < 8; j++) {
                float y = part[i][j] - cmp[i][j];
                float t = acc[i][j] + y;
                cmp[i][j] = (t - acc[i][j]) - y;
                acc[i][j] = t;
            }
        if (k0 < K) {
            int nb = buf ^ 1;
            As[nb][ac + 0][ar] = a0.x; As[nb][ac + 1][ar] = a0.y;
            As[nb][ac + 2][ar] = a0.z; As[nb][ac + 3][ar] = a0.w;
            As[nb][ac + 4][ar] = a1.x; As[nb][ac + 5][ar] = a1.y;
            As[nb][ac + 6][ar] = a1.z; As[nb][ac + 7][ar] = a1.w;
            *(float4*)&Bs[nb][br][bc]     = b0;
            *(float4*)&Bs[nb][br][bc + 4] = b1;
            __syncthreads();
            buf = nb;
        }
    }
    #pragma unroll
    for (int i = 0; i < 8; i++) {
        int row = m0 + ((i < 4) ? (ty * 4 + i) : (64 + ty * 4 + (i - 4)));
        float4 v0 = make_float4(acc[i][0], acc[i][1], acc[i][2], acc[i][3]);
        float4 v1 = make_float4(acc[i][4], acc[i][5], acc[i][6], acc[i][7]);
        *(float4*)(C + (size_t)row * N + n0 + tx * 4) = v0;
        *(float4*)(C + (size_t)row * N + n0 + 64 + tx * 4) = v1;
    }
}

// ---------------- FWHT over length-128 vectors, scaled by 128^-0.5 ----------------
__global__ void hadamard_kernel(float* __restrict__ buf, int nvec) {
    int gwarp = (blockIdx.x * blockDim.x + threadIdx.x) >> 5;
    int lane = threadIdx.x & 31;
    if (gwarp >= nvec) return;
    float* p = buf + (size_t)gwarp * 128;
    float4 v = *(const float4*)(p + lane * 4);
    float a, b;
    a = v.x + v.y; b = v.x - v.y; v.x = a; v.y = b;
    a = v.z + v.w; b = v.z - v.w; v.z = a; v.w = b;
    a = v.x + v.z; b = v.x - v.z; v.x = a; v.z = b;
    a = v.y + v.w; b = v.y - v.w; v.y = a; v.w = b;
    #pragma unroll
    for (int m = 1; m <= 16; m <<= 1) {
        float ox = __shfl_xor_sync(0xFFFFFFFFu, v.x, m);
        float oy = __shfl_xor_sync(0xFFFFFFFFu, v.y, m);
        float oz = __shfl_xor_sync(0xFFFFFFFFu, v.z, m);
        float ow = __shfl_xor_sync(0xFFFFFFFFu, v.w, m);
        bool up = (lane & m) == 0;
        v.x = up ? v.x + ox : ox - v.x;
        v.y = up ? v.y + oy : oy - v.y;
        v.z = up ? v.z + oz : oz - v.z;
        v.w = up ? v.w + ow : ow - v.w;
    }
    const float s = 0.08838834764831845f; // 128^-0.5
    v.x *= s; v.y *= s; v.z *= s; v.w *= s;
    *(float4*)(p + lane * 4) = v;
}

// ---------------- indexing logits: I[t,s] = sum_h iw[t,h]*relu(qi[t,h,:].ki[s,:]) ----
__global__ void __launch_bounds__(256) logits_kernel() {
    int bt = blockIdx.y, bs = blockIdx.x;
    int t0 = bt * 128, s0 = bs * 64;
    if (s0 > t0 + 127) return;                 // fully above diagonal
    __shared__ float Bs[128][64];              // ki^T, XOR-swizzled  (32KB)
    __shared__ float As[16][128];              // qi chunk^T, swizzled (8KB)
    __shared__ float iws[128][16];             // (8KB)  -> total 48KB
    int tid = threadIdx.x;
    int txs = tid & 15, tyt = tid >> 4;

    // iw tile 128x16
    #pragma unroll
    for (int rep = 0; rep < 2; rep++) {
        int q = tid + rep * 256;               // 0..511 float4s
        int r = q >> 2, c = (q & 3) * 4;
        float4 w = *(const float4*)(g_iw + (size_t)(t0 + r) * HI + c);
        *(float4*)&iws[r][c] = w;
    }
    // ki tile 64 x 128, transposed + swizzled: Bs[k][ s ^ ((k&15)<<2) ]
    #pragma unroll
    for (int rep = 0; rep < 8; rep++) {
        int q = tid + rep * 256;               // 0..2047
        int r = q >> 5;                        // s row 0..63
        int c = (q & 31) * 4;                  // k base
        float4 w = *(const float4*)(g_ki + (size_t)(s0 + r) * DI + c);
        Bs[c + 0][r ^ (((c + 0) & 15) << 2)] = w.x;
        Bs[c + 1][r ^ (((c + 1) & 15) << 2)] = w.y;
        Bs[c + 2][r ^ (((c + 2) & 15) << 2)] = w.z;
        Bs[c + 3][r ^ (((c + 3) & 15) << 2)] = w.w;
    }

    double facc[8][4] = {};
    for (int h = 0; h < HI; h++) {
        double hacc[8][4] = {};
        float  cacc[8][4] = {};
        for (int c16 = 0; c16 < 8; c16++) {
            __syncthreads();   // protect As reuse (also covers initial Bs/iws fill)
            // qi chunk 128 x 16 at k-cols [h*128 + c16*16, +16)
            #pragma unroll
            for (int rep = 0; rep < 2; rep++) {
                int q = tid + rep * 256;       // 0..511 float4s
                int r = q >> 2;                // t row 0..127
                int c = (q & 3) * 4;           // k within 16
                float4 w = *(const float4*)(g_qi + (size_t)(t0 + r) * DM
                                            + h * 128 + c16 * 16 + c);
                As[c + 0][r ^ (((c + 0) & 15) << 2)] = w.x;
                As[c + 1][r ^ (((c + 1) & 15) << 2)] = w.y;
                As[c + 2][r ^ (((c + 2) & 15) << 2)] = w.z;
                As[c + 3][r ^ (((c + 3) & 15) << 2)] = w.w;
            }
            __syncthreads();
            #pragma unroll
            for (int k = 0; k < 16; k++) {
                int kk = c16 * 16 + k;
                int swa = (k & 15) << 2;
                int swb = (kk & 15) << 2;
                float af[8], bf[4];
                *(float4*)&af[0] = *(const float4*)&As[k][(tyt * 4) ^ swa];
                *(float4*)&af[4] = *(const float4*)&As[k][64 + ((tyt * 4) ^ swa)];
                *(float4*)&bf[0] = *(const float4*)&Bs[kk][(txs * 4) ^ swb];
                #pragma unroll
                for (int i = 0; i < 8; i++)
                    #pragma unroll
                    for (int j = 0; j < 4; j++)
                        cacc[i][j] = fmaf(af[i], bf[j], cacc[i][j]);
            }
            if (c16 & 1) {   // 32-k boundary: promote to double (round-2 cadence)
                #pragma unroll
                for (int i = 0; i < 8; i++)
                    #pragma unroll
                    for (int j = 0; j < 4; j++) {
                        hacc[i][j] += (double)cacc[i][j];
                        cacc[i][j] = 0.f;
                    }
            }
        }
        #pragma unroll
        for (int i = 0; i < 8; i++) {
            int trow = (i < 4) ? (tyt * 4 + i) : (64 + tyt * 4 + (i - 4));
            double w = (double)iws[trow][h];
            #pragma unroll
            for (int j = 0; j < 4; j++) {
                double r = hacc[i][j] > 0.0 ? hacc[i][j] : 0.0;
                facc[i][j] += w * r;
            }
        }
    }
    #pragma unroll
    for (int i = 0; i < 8; i++) {
        int trow = (i < 4) ? (tyt * 4 + i) : (64 + tyt * 4 + (i - 4));
        #pragma unroll
        for (int j = 0; j < 4; j++)
            g_I[(size_t)(t0 + trow) * SQ + s0 + txs * 4 + j] = (float)facc[i][j];
    }
}

// ---------------- exact top-256 per row (causal: s in [0, t]) ----------------
__device__ __forceinline__ unsigned f2key(float f) {
    unsigned u = __float_as_uint(f);
    return (u & 0x80000000u) ? ~u : (u | 0x80000000u);
}

// selection via 4-round byte-radix histogram (exact kth-largest key — identical
// threshold to the former 32-round binary search, ~8x fewer scans/barriers).
__global__ void topk_kernel() {
    int t = blockIdx.x;
    int tid = threadIdx.x;
    int n = t + 1;
    __shared__ unsigned keys[2048];
    __shared__ int hist[256];
    __shared__ int wsum[8];
    __shared__ unsigned prefix_sh;
    __shared__ int kth_sh;
    __shared__ int red[8];
    __shared__ int cnt_sh;
    __shared__ int pos_sh;
    __shared__ int tcnt[256];

    if (n <= TOPKK) {
        g_idx[t * TOPKK + tid] = (tid < n) ? tid : 0;
        if (tid == 0) g_nv[t] = n;
        return;
    }
    const float* row = g_I + (size_t)t * SQ;
    for (int i = tid; i < n; i += 256) keys[i] = f2key(row[i]);
    if (tid == 0) { prefix_sh = 0; kth_sh = TOPKK; }
    __syncthreads();

    int lane = tid & 31, warp = tid >> 5;

    #pragma unroll
    for (int rnd = 0; rnd < 4; rnd++) {
        int shift = 24 - 8 * rnd;
        hist[tid] = 0;
        __syncthreads();
        unsigned pfx = prefix_sh;
        unsigned mask = (rnd == 0) ? 0u : (0xFFFFFFFFu << (shift + 8));
        for (int i = tid; i < n; i += 256) {
            unsigned k = keys[i];
            if ((k & mask) == pfx)
                atomicAdd(&hist[(k >> shift) & 255], 1);
        }
        __syncthreads();
        // two-level suffix search: warp partials, then serial within one warp range
        int v = hist[warp * 32 + lane];
        int s = v;
        #pragma unroll
        for (int o = 16; o; o >>= 1) s += __shfl_down_sync(0xFFFFFFFFu, s, o);
        if (lane == 0) wsum[warp] = s;
        __syncthreads();
        if (tid == 0) {
            int kth = kth_sh;
            int acc = 0;
            int w = 7;
            for (; w > 0; w--) {
                if (acc + wsum[w] >= kth) break;
                acc += wsum[w];
            }
            int b = w * 32 + 31;
            for (;; b--) {
                int h = hist[b];
                if (acc + h >= kth) { kth_sh = kth - acc; break; }
                acc += h;
            }
            prefix_sh = prefix_sh | ((unsigned)b << shift);
        }
        __syncthreads();
    }
    unsigned thr = prefix_sh;  // exact key of the 256th largest

    // count strictly-greater
    int c = 0;
    for (int i = tid; i < n; i += 256) c += (keys[i] > thr);
    #pragma unroll
    for (int o = 16; o; o >>= 1) c += __shfl_down_sync(0xFFFFFFFFu, c, o);
    if (lane == 0) red[warp] = c;
    __syncthreads();
    if (tid == 0) {
        int s = 0;
        #pragma unroll
        for (int w = 0; w < 8; w++) s += red[w];
        cnt_sh = s;
        pos_sh = 0;
    }
    __syncthreads();
    int c_gt = cnt_sh;

    // compact strictly-greater (order within top-k is irrelevant downstream)
    for (int i = tid; i < n; i += 256) {
        if (keys[i] > thr) {
            int p = atomicAdd(&pos_sh, 1);
            g_idx[t * TOPKK + p] = i;
        }
    }
    // ties == thr: take lowest (256 - c_gt) indices -> matches jax tie-break
    int lo = tid * 8, hi = min(n, lo + 8);
    int myt = 0;
    for (int i = lo; i < hi; i++) myt += (keys[i] == thr);
    tcnt[tid] = myt;
    __syncthreads();
    if (tid == 0) {
        int s = 0;
        for (int i = 0; i < 256; i++) { int v2 = tcnt[i]; tcnt[i] = s; s += v2; }
    }
    __syncthreads();
    int rem = TOPKK - c_gt;
    int r = tcnt[tid];
    for (int i = lo; i < hi; i++) {
        if (keys[i] == thr) {
            if (r < rem) g_idx[t * TOPKK + c_gt + r] = i;
            r++;
        }
    }
    if (tid == 0) g_nv[t] = TOPKK;
}

// ---------------- gathered attention over the top-256 keys ----------------
__global__ void attn_kernel() {
    int t = blockIdx.x, tid = threadIdx.x;
    __shared__ float q_s[NH * HD];
    __shared__ int   idx_s[TOPKK];
    __shared__ float kv[32 * 129];
    __shared__ float sc[NH * TOPKK];

    int nv = g_nv[t];
    for (int i = tid; i < NH * HD; i += 256) q_s[i] = g_q[(size_t)t * DM + i];
    idx_s[tid] = g_idx[t * TOPKK + tid];
    __syncthreads();

    int lane = tid & 31, warp = tid >> 5;
    const float scale = 0.08838834764831845f;

    for (int c0 = 0; c0 < TOPKK; c0 += 32) {
        #pragma unroll
        for (int rr = 0; rr < 4; rr++) {
            int r = warp * 4 + rr;
            const float* src = g_k + (size_t)idx_s[c0 + r] * HD;
            #pragma unroll
            for (int jj = 0; jj < 4; jj++)
                kv[r * 129 + jj * 32 + lane] = src[jj * 32 + lane];
        }
        __syncthreads();
        int kl = lane, hh = warp;
        #pragma unroll
        for (int hp = 0; hp < 2; hp++) {
            int h = hh + hp * 8;
            const float* qp = &q_s[h * HD];
            const float* kp = &kv[kl * 129];
            float d0 = 0.f, d1 = 0.f, d2 = 0.f, d3 = 0.f;
            #pragma unroll 8
            for (int d = 0; d < HD; d += 4) {
                d0 = fmaf(qp[d + 0], kp[d + 0], d0);
                d1 = fmaf(qp[d + 1], kp[d + 1], d1);
                d2 = fmaf(qp[d + 2], kp[d + 2], d2);
                d3 = fmaf(qp[d + 3], kp[d + 3], d3);
            }
            float dot = (d0 + d1) + (d2 + d3);
            sc[h * TOPKK + c0 + kl] = (c0 + kl < nv) ? dot * scale : NEGV;
        }
        __syncthreads();
    }

    #pragma unroll
    for (int hp = 0; hp < 2; hp++) {
        int h = warp + hp * 8;
        float vals[8];
        float m = -1e38f;
        #pragma unroll
        for (int j = 0; j < 8; j++) {
            vals[j] = sc[h * TOPKK + lane + 32 * j];
            m = fmaxf(m, vals[j]);
        }
        #pragma unroll
        for (int o = 16; o; o >>= 1) m = fmaxf(m, __shfl_xor_sync(0xFFFFFFFFu, m, o));
        float s = 0.f;
        #pragma unroll
        for (int j = 0; j < 8; j++) { vals[j] = expf(vals[j] - m); s += vals[j]; }
        #pragma unroll
        for (int o = 16; o; o >>= 1) s += __shfl_xor_sync(0xFFFFFFFFu, s, o);
        float inv = 1.f / s;
        #pragma unroll
        for (int j = 0; j < 8; j++) sc[h * TOPKK + lane + 32 * j] = vals[j] * inv;
    }
    __syncthreads();

    int d = tid & 127, hpair = tid >> 7;
    float acc[8] = {};
    for (int c0 = 0; c0 < TOPKK; c0 += 32) {
        #pragma unroll
        for (int rr = 0; rr < 4; rr++) {
            int r = warp * 4 + rr;
            const float* src = g_v + (size_t)idx_s[c0 + r] * HD;
            #pragma unroll
            for (int jj = 0; jj < 4; jj++)
                kv[r * 129 + jj * 32 + lane] = src[jj * 32 + lane];
        }
        __syncthreads();
        #pragma unroll
        for (int kk = 0; kk < 32; kk++) {
            float vv = kv[kk * 129 + d];
            #pragma unroll
            for (int j = 0; j < 8; j++)
                acc[j] = fmaf(sc[(hpair * 8 + j) * TOPKK + c0 + kk], vv, acc[j]);
        }
        __syncthreads();
    }
    #pragma unroll
    for (int j = 0; j < 8; j++)
        g_o[(size_t)t * DM + (hpair * 8 + j) * HD + d] = acc[j];
}

// ---------------- launch ----------------
extern "C" void kernel_launch(void* const* d_in, const int* in_sizes, int n_in,
                              void* d_out, int out_size) {
    const float* x      = (const float*)d_in[0];
    const float* wq_idx = (const float*)d_in[1];
    const float* wk_idx = (const float*)d_in[2];
    const float* w_iw   = (const float*)d_in[3];
    const float* wq     = (const float*)d_in[4];
    const float* wk     = (const float*)d_in[5];
    const float* wv     = (const float*)d_in[6];
    const float* wo     = (const float*)d_in[7];
    float* out = (float*)d_out;

    float *qi, *ki, *q, *o;
    cudaGetSymbolAddress((void**)&qi, g_qi);
    cudaGetSymbolAddress((void**)&ki, g_ki);
    cudaGetSymbolAddress((void**)&q,  g_q);
    cudaGetSymbolAddress((void**)&o,  g_o);

    dim3 blk(256);
    // index-path big projection (Kahan fp32 — numerics untouched)
    sgemm128k<<<dim3(DM / 128, SQ / 128), blk>>>(x, wq_idx, qi, SQ, DM, DM);
    // fused small projections: ki, iw, k, v — ONE launch, 224 CTAs
    sgemm64_multi<<<dim3(7, SQ / 64), blk>>>(x, wk_idx, w_iw, wk, wv, SQ, DM);
    // attention-path big projection: split-bf16 HMMA (prefetched)
    gemm_mma<<<dim3(DM / 128, SQ / 128), blk>>>(x, wq, q, SQ, DM, DM);
    // hadamard
    hadamard_kernel<<<(SQ * HI) / 8, 256>>>(qi, SQ * HI);
    hadamard_kernel<<<SQ / 8, 256>>>(ki, SQ);
    // indexing logits (lower-triangular 128x64 tiles)
    logits_kernel<<<dim3(SQ / 64, SQ / 128), blk>>>();
    // exact top-256 (byte-radix selection)
    topk_kernel<<<SQ, 256>>>();
    // gathered attention
    attn_kernel<<<SQ, 256>>>();
    // output projection: split-bf16 HMMA (prefetched)
    gemm_mma<<<dim3(DM / 128, SQ / 128), blk>>>(o, wo, out, SQ, DM, DM);
}

// round 13
// speedup vs baseline: 1.0620x; 1.0620x over previous
#include <cuda_runtime.h>
#include <cuda.h>
#include <cuda_bf16.h>
#include <cstdint>
#include <math.h>

#define SQ   2048   // sequence
#define DM   2048   // model dim
#define HI   16     // index heads
#define DI   128    // index head dim
#define NH   16     // attn heads
#define HD   128    // attn head dim
#define TOPKK 256
#define NEGV -1e30f

// ---------------- scratch (static device allocations) ----------------
__device__ float g_qi[SQ * DM];     // x @ wq_idx  (then hadamard per 128)
__device__ float g_ki[SQ * DI];     // x @ wk_idx  (then hadamard)
__device__ float g_iw[SQ * HI];     // x @ w_iw
__device__ float g_q [SQ * DM];     // x @ wq
__device__ float g_k [SQ * HD];     // x @ wk
__device__ float g_v [SQ * HD];     // x @ wv
__device__ float g_I [SQ * SQ];     // indexing logits (lower triangle valid)
__device__ int   g_idx[SQ * TOPKK];
__device__ int   g_nv [SQ];
__device__ float g_o [SQ * DM];     // attention output (pre-wo)

// ======================= mma.sync helpers ====================================
__device__ __forceinline__ uint32_t s2u(const void* p) {
    uint32_t a;
    asm("{ .reg .u64 t; cvta.to.shared.u64 t, %1; cvt.u32.u64 %0, t; }"
        : "=r"(a) : "l"(p));
    return a;
}

__device__ __forceinline__ void ldm_x4(uint32_t* r, uint32_t addr) {
    asm volatile("ldmatrix.sync.aligned.m8n8.x4.shared.b16 {%0,%1,%2,%3}, [%4];"
                 : "=r"(r[0]), "=r"(r[1]), "=r"(r[2]), "=r"(r[3]) : "r"(addr));
}
__device__ __forceinline__ void ldm_x2t(uint32_t* r, uint32_t addr) {
    asm volatile("ldmatrix.sync.aligned.m8n8.x2.trans.shared.b16 {%0,%1}, [%2];"
                 : "=r"(r[0]), "=r"(r[1]) : "r"(addr));
}
__device__ __forceinline__ void mma16816(float* c, const uint32_t* a, const uint32_t* b) {
    asm volatile(
        "mma.sync.aligned.m16n8k16.row.col.f32.bf16.bf16.f32 "
        "{%0,%1,%2,%3}, {%4,%5,%6,%7}, {%8,%9}, {%0,%1,%2,%3};"
        : "+f"(c[0]), "+f"(c[1]), "+f"(c[2]), "+f"(c[3])
        : "r"(a[0]), "r"(a[1]), "r"(a[2]), "r"(a[3]), "r"(b[0]), "r"(b[1]));
}

// split two fp32 into packed bf16x2 (hi) and residual bf16x2 (lo)
__device__ __forceinline__ void split2(float a, float b, uint32_t& hi, uint32_t& lo) {
    __nv_bfloat16 ah = __float2bfloat16(a), bh = __float2bfloat16(b);
    __nv_bfloat16 al = __float2bfloat16(a - __bfloat162float(ah));
    __nv_bfloat16 bl = __float2bfloat16(b - __bfloat162float(bh));
    hi = ((uint32_t)__bfloat16_as_ushort(bh) << 16) | (uint32_t)__bfloat16_as_ushort(ah);
    lo = ((uint32_t)__bfloat16_as_ushort(bl) << 16) | (uint32_t)__bfloat16_as_ushort(al);
}

// ---------------- split-bf16 HMMA GEMM: C[M,N] = A[M,K] @ B[K,N] -------------
// 128x128 CTA tile, 8 warps (2x4), warp tile 64x32, BK=32, mma.m16n8k16.
// 3-product split (hi*hi + hi*lo + lo*hi): error ~2^-18. Attention path only.
// (R11 body — the R12 register-prefetch variant spilled and regressed.)
__global__ void __launch_bounds__(256) gemm_mma(
        const float* __restrict__ A, const float* __restrict__ B,
        float* __restrict__ C, int M, int N, int K) {
    __shared__ __nv_bfloat16 Ahi[128][40], Alo[128][40];     // 80B stride
    __shared__ __nv_bfloat16 Bhi[32][128], Blo[32][128];     // XOR-swizzled rows
    int tid = threadIdx.x, lane = tid & 31, wid = tid >> 5;
    int wm = wid >> 2, wn = wid & 3;
    int m0 = blockIdx.y * 128, n0 = blockIdx.x * 128;

    float acc[4][4][4] = {};

    uint32_t bhi_base = s2u(&Bhi[0][0]);
    uint32_t blo_base = s2u(&Blo[0][0]);

    for (int k0 = 0; k0 < K; k0 += 32) {
        // ---- fill A tile: 128 rows x 32 k-cols ----
        #pragma unroll
        for (int rep = 0; rep < 4; rep++) {
            int q = tid + rep * 256;           // 0..1023
            int row = q >> 3, c4 = (q & 7) * 4;
            float4 f = *(const float4*)(A + (size_t)(m0 + row) * K + k0 + c4);
            uint32_t h0, l0, h1, l1;
            split2(f.x, f.y, h0, l0);
            split2(f.z, f.w, h1, l1);
            *(uint2*)&Ahi[row][c4] = make_uint2(h0, h1);
            *(uint2*)&Alo[row][c4] = make_uint2(l0, l1);
        }
        // ---- fill B tile: 32 k-rows x 128 n-cols, swizzled ----
        #pragma unroll
        for (int rep = 0; rep < 4; rep++) {
            int q = tid + rep * 256;           // 0..1023
            int row = q >> 5, n4 = (q & 31) * 4;
            float4 f = *(const float4*)(B + (size_t)(k0 + row) * N + n0 + n4);
            uint32_t h0, l0, h1, l1;
            split2(f.x, f.y, h0, l0);
            split2(f.z, f.w, h1, l1);
            uint32_t off = (uint32_t)(row * 256) + (((uint32_t)(n4 * 2)) ^ (((uint32_t)(row & 7)) << 4));
            *(uint2*)((char*)Bhi + off) = make_uint2(h0, h1);
            *(uint2*)((char*)Blo + off) = make_uint2(l0, l1);
        }
        __syncthreads();

        #pragma unroll
        for (int ks = 0; ks < 2; ks++) {
            int kc = ks * 16;
            uint32_t ah[4][4], al[4][4], bh[4][2], bl[4][2];
            int r = lane & 7, mt = lane >> 3;
            int arow = (mt & 1) * 8 + r;
            int acol = kc + (mt >> 1) * 8;
            #pragma unroll
            for (int mi = 0; mi < 4; mi++) {
                int row = wm * 64 + mi * 16 + arow;
                ldm_x4(ah[mi], s2u(&Ahi[row][acol]));
                ldm_x4(al[mi], s2u(&Alo[row][acol]));
            }
            int krow = kc + (lane & 15);
            uint32_t ksw = ((uint32_t)(krow & 7)) << 4;
            #pragma unroll
            for (int ni = 0; ni < 4; ni++) {
                int nb = wn * 32 + ni * 8;
                uint32_t boff = (uint32_t)(krow * 256) + (((uint32_t)(nb * 2)) ^ ksw);
                ldm_x2t(bh[ni], bhi_base + boff);
                ldm_x2t(bl[ni], blo_base + boff);
            }
            #pragma unroll
            for (int mi = 0; mi < 4; mi++)
                #pragma unroll
                for (int ni = 0; ni < 4; ni++) {
                    mma16816(acc[mi][ni], ah[mi], bh[ni]);
                    mma16816(acc[mi][ni], ah[mi], bl[ni]);
                    mma16816(acc[mi][ni], al[mi], bh[ni]);
                }
        }
        __syncthreads();
    }

    // ---- epilogue ----
    int g = lane >> 2, tig = lane & 3;
    #pragma unroll
    for (int mi = 0; mi < 4; mi++) {
        int row = m0 + wm * 64 + mi * 16 + g;
        #pragma unroll
        for (int ni = 0; ni < 4; ni++) {
            int col = n0 + wn * 32 + ni * 8 + tig * 2;
            *(float2*)(C + (size_t)row * N + col) =
                make_float2(acc[mi][ni][0], acc[mi][ni][1]);
            *(float2*)(C + (size_t)(row + 8) * N + col) =
                make_float2(acc[mi][ni][2], acc[mi][ni][3]);
        }
    }
}

// ---------------- fused small-N GEMMs: ki / iw / k / v in ONE launch ---------
__global__ void sgemm64_multi(const float* __restrict__ A,
                              const float* __restrict__ Bki,
                              const float* __restrict__ Biw,
                              const float* __restrict__ Bk,
                              const float* __restrict__ Bv,
                              int M, int K) {
    __shared__ float As[16][64];   // [k][m]
    __shared__ float Bs[16][64];   // [k][n]
    int tid = threadIdx.x;
    int tx = tid & 15, ty = tid >> 4;
    int m0 = blockIdx.y * 64;

    const float* B; float* C; int n0; int N;
    switch (blockIdx.x) {
        case 0: B = Bki; C = g_ki; n0 = 0;  N = DI; break;
        case 1: B = Bki; C = g_ki; n0 = 64; N = DI; break;
        case 2: B = Biw; C = g_iw; n0 = 0;  N = HI; break;
        case 3: B = Bk;  C = g_k;  n0 = 0;  N = HD; break;
        case 4: B = Bk;  C = g_k;  n0 = 64; N = HD; break;
        case 5: B = Bv;  C = g_v;  n0 = 0;  N = HD; break;
        default: B = Bv; C = g_v;  n0 = 64; N = HD; break;
    }

    int a_r = tid >> 2;          // 0..63
    int a_c = (tid & 3) * 4;     // 0..12
    int b_r = tid >> 4;          // 0..15
    int b_c = (tid & 15) * 4;    // 0..60

    float acc[4][4] = {};
    float cmp[4][4] = {};

    for (int k0 = 0; k0 < K; k0 += 16) {
        float4 av = *(const float4*)(A + (size_t)(m0 + a_r) * K + k0 + a_c);
        As[a_c + 0][a_r] = av.x; As[a_c + 1][a_r] = av.y;
        As[a_c + 2][a_r] = av.z; As[a_c + 3][a_r] = av.w;
        const float* bg = B + (size_t)(k0 + b_r) * N + n0 + b_c;
        float4 bv;
        if (n0 + b_c + 3 < N) {
            bv = *(const float4*)bg;
        } else {
            bv.x = (n0 + b_c + 0 < N) ? bg[0] : 0.f;
            bv.y = (n0 + b_c + 1 < N) ? bg[1] : 0.f;
            bv.z = (n0 + b_c + 2 < N) ? bg[2] : 0.f;
            bv.w = (n0 + b_c + 3 < N) ? bg[3] : 0.f;
        }
        *(float4*)&Bs[b_r][b_c] = bv;
        __syncthreads();

        float part[4][4] = {};
        #pragma unroll
        for (int k = 0; k < 16; k++) {
            float4 a4 = *(const float4*)&As[k][ty * 4];
            float4 b4 = *(const float4*)&Bs[k][tx * 4];
            float ar[4] = {a4.x, a4.y, a4.z, a4.w};
            float br[4] = {b4.x, b4.y, b4.z, b4.w};
            #pragma unroll
            for (int i = 0; i < 4; i++)
                #pragma unroll
                for (int j = 0; j < 4; j++)
                    part[i][j] = fmaf(ar[i], br[j], part[i][j]);
        }
        #pragma unroll
        for (int i = 0; i < 4; i++)
            #pragma unroll
            for (int j = 0; j < 4; j++) {
                float y = part[i][j] - cmp[i][j];
                float t = acc[i][j] + y;
                cmp[i][j] = (t - acc[i][j]) - y;
                acc[i][j] = t;
            }
        __syncthreads();
    }
    #pragma unroll
    for (int i = 0; i < 4; i++) {
        int r = m0 + ty * 4 + i;
        #pragma unroll
        for (int j = 0; j < 4; j++) {
            int c = n0 + tx * 4 + j;
            if (c < N) C[(size_t)r * N + c] = acc[i][j];
        }
    }
}

// ---------------- big SGEMM with per-16-k-tile Kahan (index path: qi) --------
__global__ void __launch_bounds__(256) sgemm128k(
        const float* __restrict__ A, const float* __restrict__ B,
        float* __restrict__ C, int M, int N, int K) {
    __shared__ float As[2][16][132];  // 528B row stride (16B-aligned)
    __shared__ float Bs[2][16][128];
    int tid = threadIdx.x;
    int tx = tid & 15, ty = tid >> 4;
    int m0 = blockIdx.y * 128, n0 = blockIdx.x * 128;

    int ar = tid >> 1, ac = (tid & 1) * 8;   // A: 128 rows x 16 cols (2 float4)
    int br = tid >> 4, bc = (tid & 15) * 8;  // B: 16 rows x 128 cols (2 float4)

    const float* Ap = A + (size_t)(m0 + ar) * K + ac;
    const float* Bp = B + (size_t)br * N + n0 + bc;

    float acc[8][8] = {};
    float cmp[8][8] = {};

    { // tile 0
        float4 a0 = *(const float4*)Ap;
        float4 a1 = *(const float4*)(Ap + 4);
        As[0][ac + 0][ar] = a0.x; As[0][ac + 1][ar] = a0.y;
        As[0][ac + 2][ar] = a0.z; As[0][ac + 3][ar] = a0.w;
        As[0][ac + 4][ar] = a1.x; As[0][ac + 5][ar] = a1.y;
        As[0][ac + 6][ar] = a1.z; As[0][ac + 7][ar] = a1.w;
        *(float4*)&Bs[0][br][bc]     = *(const float4*)Bp;
        *(float4*)&Bs[0][br][bc + 4] = *(const float4*)(Bp + 4);
    }
    __syncthreads();

    int buf = 0;
    for (int k0 = 16; k0 <= K; k0 += 16) {
        float4 a0, a1, b0, b1;
        if (k0 < K) {
            a0 = *(const float4*)(Ap + k0);
            a1 = *(const float4*)(Ap + k0 + 4);
            b0 = *(const float4*)(Bp + (size_t)k0 * N);
            b1 = *(const float4*)(Bp + (size_t)k0 * N + 4);
        }
        float part[8][8] = {};
        #pragma unroll
        for (int k = 0; k < 16; k++) {
            float af[8], bf[8];
            *(float4*)&af[0] = *(const float4*)&As[buf][k][ty * 4];
            *(float4*)&af[4] = *(const float4*)&As[buf][k][64 + ty * 4];
            *(float4*)&bf[0] = *(const float4*)&Bs[buf][k][tx * 4];
            *(float4*)&bf[4] = *(const float4*)&Bs[buf][k][64 + tx * 4];
            #pragma unroll
            for (int i = 0; i < 8; i++)
                #pragma unroll
                for (int j = 0; j < 8; j++)
                    part[i][j] = fmaf(af[i], bf[j], part[i][j]);
        }
        #pragma unroll
        for (int i = 0; i < 8; i++)
            #pragma unroll
            for (int j = 0; j < 8; j++) {
                float y = part[i][j] - cmp[i][j];
                float t = acc[i][j] + y;
                cmp[i][j] = (t - acc[i][j]) - y;
                acc[i][j] = t;
            }
        if (k0 < K) {
            int nb = buf ^ 1;
            As[nb][ac + 0][ar] = a0.x; As[nb][ac + 1][ar] = a0.y;
            As[nb][ac + 2][ar] = a0.z; As[nb][ac + 3][ar] = a0.w;
            As[nb][ac + 4][ar] = a1.x; As[nb][ac + 5][ar] = a1.y;
            As[nb][ac + 6][ar] = a1.z; As[nb][ac + 7][ar] = a1.w;
            *(float4*)&Bs[nb][br][bc]     = b0;
            *(float4*)&Bs[nb][br][bc + 4] = b1;
            __syncthreads();
            buf = nb;
        }
    }
    #pragma unroll
    for (int i = 0; i < 8; i++) {
        int row = m0 + ((i < 4) ? (ty * 4 + i) : (64 + ty * 4 + (i - 4)));
        float4 v0 = make_float4(acc[i][0], acc[i][1], acc[i][2], acc[i][3]);
        float4 v1 = make_float4(acc[i][4], acc[i][5], acc[i][6], acc[i][7]);
        *(float4*)(C + (size_t)row * N + n0 + tx * 4) = v0;
        *(float4*)(C + (size_t)row * N + n0 + 64 + tx * 4) = v1;
    }
}

// ---------------- FWHT over length-128 vectors, scaled by 128^-0.5 ----------------
__global__ void hadamard_kernel(float* __restrict__ buf, int nvec) {
    int gwarp = (blockIdx.x * blockDim.x + threadIdx.x) >> 5;
    int lane = threadIdx.x & 31;
    if (gwarp >= nvec) return;
    float* p = buf + (size_t)gwarp * 128;
    float4 v = *(const float4*)(p + lane * 4);
    float a, b;
    a = v.x + v.y; b = v.x - v.y; v.x = a; v.y = b;
    a = v.z + v.w; b = v.z - v.w; v.z = a; v.w = b;
    a = v.x + v.z; b = v.x - v.z; v.x = a; v.z = b;
    a = v.y + v.w; b = v.y - v.w; v.y = a; v.w = b;
    #pragma unroll
    for (int m = 1; m <= 16; m <<= 1) {
        float ox = __shfl_xor_sync(0xFFFFFFFFu, v.x, m);
        float oy = __shfl_xor_sync(0xFFFFFFFFu, v.y, m);
        float oz = __shfl_xor_sync(0xFFFFFFFFu, v.z, m);
        float ow = __shfl_xor_sync(0xFFFFFFFFu, v.w, m);
        bool up = (lane & m) == 0;
        v.x = up ? v.x + ox : ox - v.x;
        v.y = up ? v.y + oy : oy - v.y;
        v.z = up ? v.z + oz : oz - v.z;
        v.w = up ? v.w + ow : ow - v.w;
    }
    const float s = 0.08838834764831845f; // 128^-0.5
    v.x *= s; v.y *= s; v.z *= s; v.w *= s;
    *(float4*)(p + lane * 4) = v;
}

// ---------------- indexing logits: I[t,s] = sum_h iw[t,h]*relu(qi[t,h,:].ki[s,:]) ----
__global__ void __launch_bounds__(256) logits_kernel() {
    int bt = blockIdx.y, bs = blockIdx.x;
    int t0 = bt * 128, s0 = bs * 64;
    if (s0 > t0 + 127) return;                 // fully above diagonal
    __shared__ float Bs[128][64];              // ki^T, XOR-swizzled  (32KB)
    __shared__ float As[16][128];              // qi chunk^T, swizzled (8KB)
    __shared__ float iws[128][16];             // (8KB)  -> total 48KB
    int tid = threadIdx.x;
    int txs = tid & 15, tyt = tid >> 4;

    // iw tile 128x16
    #pragma unroll
    for (int rep = 0; rep < 2; rep++) {
        int q = tid + rep * 256;               // 0..511 float4s
        int r = q >> 2, c = (q & 3) * 4;
        float4 w = *(const float4*)(g_iw + (size_t)(t0 + r) * HI + c);
        *(float4*)&iws[r][c] = w;
    }
    // ki tile 64 x 128, transposed + swizzled: Bs[k][ s ^ ((k&15)<<2) ]
    #pragma unroll
    for (int rep = 0; rep < 8; rep++) {
        int q = tid + rep * 256;               // 0..2047
        int r = q >> 5;                        // s row 0..63
        int c = (q & 31) * 4;                  // k base
        float4 w = *(const float4*)(g_ki + (size_t)(s0 + r) * DI + c);
        Bs[c + 0][r ^ (((c + 0) & 15) << 2)] = w.x;
        Bs[c + 1][r ^ (((c + 1) & 15) << 2)] = w.y;
        Bs[c + 2][r ^ (((c + 2) & 15) << 2)] = w.z;
        Bs[c + 3][r ^ (((c + 3) & 15) << 2)] = w.w;
    }

    double facc[8][4] = {};
    for (int h = 0; h < HI; h++) {
        double hacc[8][4] = {};
        float  cacc[8][4] = {};
        for (int c16 = 0; c16 < 8; c16++) {
            __syncthreads();   // protect As reuse (also covers initial Bs/iws fill)
            // qi chunk 128 x 16 at k-cols [h*128 + c16*16, +16)
            #pragma unroll
            for (int rep = 0; rep < 2; rep++) {
                int q = tid + rep * 256;       // 0..511 float4s
                int r = q >> 2;                // t row 0..127
                int c = (q & 3) * 4;           // k within 16
                float4 w = *(const float4*)(g_qi + (size_t)(t0 + r) * DM
                                            + h * 128 + c16 * 16 + c);
                As[c + 0][r ^ (((c + 0) & 15) << 2)] = w.x;
                As[c + 1][r ^ (((c + 1) & 15) << 2)] = w.y;
                As[c + 2][r ^ (((c + 2) & 15) << 2)] = w.z;
                As[c + 3][r ^ (((c + 3) & 15) << 2)] = w.w;
            }
            __syncthreads();
            #pragma unroll
            for (int k = 0; k < 16; k++) {
                int kk = c16 * 16 + k;
                int swa = (k & 15) << 2;
                int swb = (kk & 15) << 2;
                float af[8], bf[4];
                *(float4*)&af[0] = *(const float4*)&As[k][(tyt * 4) ^ swa];
                *(float4*)&af[4] = *(const float4*)&As[k][64 + ((tyt * 4) ^ swa)];
                *(float4*)&bf[0] = *(const float4*)&Bs[kk][(txs * 4) ^ swb];
                #pragma unroll
                for (int i = 0; i < 8; i++)
                    #pragma unroll
                    for (int j = 0; j < 4; j++)
                        cacc[i][j] = fmaf(af[i], bf[j], cacc[i][j]);
            }
            if (c16 & 1) {   // 32-k boundary: promote to double (round-2 cadence)
                #pragma unroll
                for (int i = 0; i < 8; i++)
                    #pragma unroll
                    for (int j = 0; j < 4; j++) {
                        hacc[i][j] += (double)cacc[i][j];
                        cacc[i][j] = 0.f;
                    }
            }
        }
        #pragma unroll
        for (int i = 0; i < 8; i++) {
            int trow = (i < 4) ? (tyt * 4 + i) : (64 + tyt * 4 + (i - 4));
            double w = (double)iws[trow][h];
            #pragma unroll
            for (int j = 0; j < 4; j++) {
                double r = hacc[i][j] > 0.0 ? hacc[i][j] : 0.0;
                facc[i][j] += w * r;
            }
        }
    }
    #pragma unroll
    for (int i = 0; i < 8; i++) {
        int trow = (i < 4) ? (tyt * 4 + i) : (64 + tyt * 4 + (i - 4));
        #pragma unroll
        for (int j = 0; j < 4; j++)
            g_I[(size_t)(t0 + trow) * SQ + s0 + txs * 4 + j] = (float)facc[i][j];
    }
}

// ---------------- exact top-256 per row (causal: s in [0, t]) ----------------
__device__ __forceinline__ unsigned f2key(float f) {
    unsigned u = __float_as_uint(f);
    return (u & 0x80000000u) ? ~u : (u | 0x80000000u);
}

// selection via 4-round byte-radix histogram (exact kth-largest key — identical
// threshold to the former 32-round binary search, ~8x fewer scans/barriers).
__global__ void topk_kernel() {
    int t = blockIdx.x;
    int tid = threadIdx.x;
    int n = t + 1;
    __shared__ unsigned keys[2048];
    __shared__ int hist[256];
    __shared__ int wsum[8];
    __shared__ unsigned prefix_sh;
    __shared__ int kth_sh;
    __shared__ int red[8];
    __shared__ int cnt_sh;
    __shared__ int pos_sh;
    __shared__ int tcnt[256];

    if (n <= TOPKK) {
        g_idx[t * TOPKK + tid] = (tid < n) ? tid : 0;
        if (tid == 0) g_nv[t] = n;
        return;
    }
    const float* row = g_I + (size_t)t * SQ;
    for (int i = tid; i < n; i += 256) keys[i] = f2key(row[i]);
    if (tid == 0) { prefix_sh = 0; kth_sh = TOPKK; }
    __syncthreads();

    int lane = tid & 31, warp = tid >> 5;

    #pragma unroll
    for (int rnd = 0; rnd < 4; rnd++) {
        int shift = 24 - 8 * rnd;
        hist[tid] = 0;
        __syncthreads();
        unsigned pfx = prefix_sh;
        unsigned mask = (rnd == 0) ? 0u : (0xFFFFFFFFu << (shift + 8));
        for (int i = tid; i < n; i += 256) {
            unsigned k = keys[i];
            if ((k & mask) == pfx)
                atomicAdd(&hist[(k >> shift) & 255], 1);
        }
        __syncthreads();
        // two-level suffix search: warp partials, then serial within one warp range
        int v = hist[warp * 32 + lane];
        int s = v;
        #pragma unroll
        for (int o = 16; o; o >>= 1) s += __shfl_down_sync(0xFFFFFFFFu, s, o);
        if (lane == 0) wsum[warp] = s;
        __syncthreads();
        if (tid == 0) {
            int kth = kth_sh;
            int acc = 0;
            int w = 7;
            for (; w > 0; w--) {
                if (acc + wsum[w] >= kth) break;
                acc += wsum[w];
            }
            int b = w * 32 + 31;
            for (;; b--) {
                int h = hist[b];
                if (acc + h >= kth) { kth_sh = kth - acc; break; }
                acc += h;
            }
            prefix_sh = prefix_sh | ((unsigned)b << shift);
        }
        __syncthreads();
    }
    unsigned thr = prefix_sh;  // exact key of the 256th largest

    // count strictly-greater
    int c = 0;
    for (int i = tid; i < n; i += 256) c += (keys[i] > thr);
    #pragma unroll
    for (int o = 16; o; o >>= 1) c += __shfl_down_sync(0xFFFFFFFFu, c, o);
    if (lane == 0) red[warp] = c;
    __syncthreads();
    if (tid == 0) {
        int s = 0;
        #pragma unroll
        for (int w = 0; w < 8; w++) s += red[w];
        cnt_sh = s;
        pos_sh = 0;
    }
    __syncthreads();
    int c_gt = cnt_sh;

    // compact strictly-greater (order within top-k is irrelevant downstream)
    for (int i = tid; i < n; i += 256) {
        if (keys[i] > thr) {
            int p = atomicAdd(&pos_sh, 1);
            g_idx[t * TOPKK + p] = i;
        }
    }
    // ties == thr: take lowest (256 - c_gt) indices -> matches jax tie-break
    int lo = tid * 8, hi = min(n, lo + 8);
    int myt = 0;
    for (int i = lo; i < hi; i++) myt += (keys[i] == thr);
    tcnt[tid] = myt;
    __syncthreads();
    if (tid == 0) {
        int s = 0;
        for (int i = 0; i < 256; i++) { int v2 = tcnt[i]; tcnt[i] = s; s += v2; }
    }
    __syncthreads();
    int rem = TOPKK - c_gt;
    int r = tcnt[tid];
    for (int i = lo; i < hi; i++) {
        if (keys[i] == thr) {
            if (r < rem) g_idx[t * TOPKK + c_gt + r] = i;
            r++;
        }
    }
    if (tid == 0) g_nv[t] = TOPKK;
}

// ---------------- gathered attention over the top-256 keys ----------------
__global__ void attn_kernel() {
    int t = blockIdx.x, tid = threadIdx.x;
    __shared__ float q_s[NH * HD];
    __shared__ int   idx_s[TOPKK];
    __shared__ float kv[32 * 129];
    __shared__ float sc[NH * TOPKK];

    int nv = g_nv[t];
    for (int i = tid; i < NH * HD; i += 256) q_s[i] = g_q[(size_t)t * DM + i];
    idx_s[tid] = g_idx[t * TOPKK + tid];
    __syncthreads();

    int lane = tid & 31, warp = tid >> 5;
    const float scale = 0.08838834764831845f;

    for (int c0 = 0; c0 < TOPKK; c0 += 32) {
        #pragma unroll
        for (int rr = 0; rr < 4; rr++) {
            int r = warp * 4 + rr;
            const float* src = g_k + (size_t)idx_s[c0 + r] * HD;
            #pragma unroll
            for (int jj = 0; jj < 4; jj++)
                kv[r * 129 + jj * 32 + lane] = src[jj * 32 + lane];
        }
        __syncthreads();
        int kl = lane, hh = warp;
        #pragma unroll
        for (int hp = 0; hp < 2; hp++) {
            int h = hh + hp * 8;
            const float* qp = &q_s[h * HD];
            const float* kp = &kv[kl * 129];
            float d0 = 0.f, d1 = 0.f, d2 = 0.f, d3 = 0.f;
            #pragma unroll 8
            for (int d = 0; d < HD; d += 4) {
                d0 = fmaf(qp[d + 0], kp[d + 0], d0);
                d1 = fmaf(qp[d + 1], kp[d + 1], d1);
                d2 = fmaf(qp[d + 2], kp[d + 2], d2);
                d3 = fmaf(qp[d + 3], kp[d + 3], d3);
            }
            float dot = (d0 + d1) + (d2 + d3);
            sc[h * TOPKK + c0 + kl] = (c0 + kl < nv) ? dot * scale : NEGV;
        }
        __syncthreads();
    }

    #pragma unroll
    for (int hp = 0; hp < 2; hp++) {
        int h = warp + hp * 8;
        float vals[8];
        float m = -1e38f;
        #pragma unroll
        for (int j = 0; j < 8; j++) {
            vals[j] = sc[h * TOPKK + lane + 32 * j];
            m = fmaxf(m, vals[j]);
        }
        #pragma unroll
        for (int o = 16; o; o >>= 1) m = fmaxf(m, __shfl_xor_sync(0xFFFFFFFFu, m, o));
        float s = 0.f;
        #pragma unroll
        for (int j = 0; j < 8; j++) { vals[j] = expf(vals[j] - m); s += vals[j]; }
        #pragma unroll
        for (int o = 16; o; o >>= 1) s += __shfl_xor_sync(0xFFFFFFFFu, s, o);
        float inv = 1.f / s;
        #pragma unroll
        for (int j = 0; j < 8; j++) sc[h * TOPKK + lane + 32 * j] = vals[j] * inv;
    }
    __syncthreads();

    int d = tid & 127, hpair = tid >> 7;
    float acc[8] = {};
    for (int c0 = 0; c0 < TOPKK; c0 += 32) {
        #pragma unroll
        for (int rr = 0; rr < 4; rr++) {
            int r = warp * 4 + rr;
            const float* src = g_v + (size_t)idx_s[c0 + r] * HD;
            #pragma unroll
            for (int jj = 0; jj < 4; jj++)
                kv[r * 129 + jj * 32 + lane] = src[jj * 32 + lane];
        }
        __syncthreads();
        #pragma unroll
        for (int kk = 0; kk < 32; kk++) {
            float vv = kv[kk * 129 + d];
            #pragma unroll
            for (int j = 0; j < 8; j++)
                acc[j] = fmaf(sc[(hpair * 8 + j) * TOPKK + c0 + kk], vv, acc[j]);
        }
        __syncthreads();
    }
    #pragma unroll
    for (int j = 0; j < 8; j++)
        g_o[(size_t)t * DM + (hpair * 8 + j) * HD + d] = acc[j];
}

// ---------------- launch ----------------
extern "C" void kernel_launch(void* const* d_in, const int* in_sizes, int n_in,
                              void* d_out, int out_size) {
    const float* x      = (const float*)d_in[0];
    const float* wq_idx = (const float*)d_in[1];
    const float* wk_idx = (const float*)d_in[2];
    const float* w_iw   = (const float*)d_in[3];
    const float* wq     = (const float*)d_in[4];
    const float* wk     = (const float*)d_in[5];
    const float* wv     = (const float*)d_in[6];
    const float* wo     = (const float*)d_in[7];
    float* out = (float*)d_out;

    float *qi, *ki, *q, *o;
    cudaGetSymbolAddress((void**)&qi, g_qi);
    cudaGetSymbolAddress((void**)&ki, g_ki);
    cudaGetSymbolAddress((void**)&q,  g_q);
    cudaGetSymbolAddress((void**)&o,  g_o);

    dim3 blk(256);
    // index-path big projection (Kahan fp32 — numerics untouched)
    sgemm128k<<<dim3(DM / 128, SQ / 128), blk>>>(x, wq_idx, qi, SQ, DM, DM);
    // fused small projections: ki, iw, k, v — ONE launch, 224 CTAs
    sgemm64_multi<<<dim3(7, SQ / 64), blk>>>(x, wk_idx, w_iw, wk, wv, SQ, DM);
    // attention-path big projection: split-bf16 HMMA
    gemm_mma<<<dim3(DM / 128, SQ / 128), blk>>>(x, wq, q, SQ, DM, DM);
    // hadamard
    hadamard_kernel<<<(SQ * HI) / 8, 256>>>(qi, SQ * HI);
    hadamard_kernel<<<SQ / 8, 256>>>(ki, SQ);
    // indexing logits (lower-triangular 128x64 tiles)
    logits_kernel<<<dim3(SQ / 64, SQ / 128), blk>>>();
    // exact top-256 (byte-radix selection)
    topk_kernel<<<SQ, 256>>>();
    // gathered attention
    attn_kernel<<<SQ, 256>>>();
    // output projection: split-bf16 HMMA
    gemm_mma<<<dim3(DM / 128, SQ / 128), blk>>>(o, wo, out, SQ, DM, DM);
}